// round 7
// baseline (speedup 1.0000x reference)
#include <cuda_runtime.h>

#define T_STEPS 50
#define BATCH   2048
#define D_IN    1156
#define H       128
#define OUT_N   10
#define KC      248          // Eigen kc (aarch64 default l1=16KB) -- verified exact

// Scratch: cur1[t][b][h] = (x[t,b,:] @ W1.T)[h]   (bias b1 added in scan)
__device__ float g_cur1[(size_t)T_STEPS * BATCH * H];  // 52.4 MB

__device__ __forceinline__ unsigned long long fma2(unsigned long long a,
                                                   unsigned long long b,
                                                   unsigned long long c) {
    unsigned long long d;
    asm("fma.rn.f32x2 %0, %1, %2, %3;" : "=l"(d) : "l"(a), "l"(b), "l"(c));
    return d;
}
__device__ __forceinline__ unsigned long long add2(unsigned long long a,
                                                   unsigned long long b) {
    unsigned long long d;
    asm("add.rn.f32x2 %0, %1, %2;" : "=l"(d) : "l"(a), "l"(b));
    return d;
}

// ---------------------------------------------------------------------------
// SGEMM emulating Eigen gebp (bit-exact, verified): KC=248 panels, each an
// ascending-k FMA chain per element, folded left-to-right in GMEM.
// Packed fp32x2 (FFMA2) math: pairs over adjacent output COLUMNS.
// A smem tile stored DUPLICATED so broadcast pairs {a,a} load directly.
// 128x128 tile, BK=8, 256 threads, 8x8 micro-tile, double-buffered smem.
// ---------------------------------------------------------------------------
__global__ __launch_bounds__(256, 2)
void gemm_xw1(const float* __restrict__ A, const float* __restrict__ W, int M, int K) {
    const int BK = 8;
    __shared__ float As2[2][BK][256];   // duplicated: [k][2r]=[k][2r+1]=A val
    __shared__ float Bs [2][BK][128];

    int tid = threadIdx.x;
    int block_m = blockIdx.x * 128;
    int tx = tid & 15;
    int ty = tid >> 4;

    unsigned long long acc2[8][4];      // [i][jj]: cols (2jj, 2jj+1), row i
#pragma unroll
    for (int i = 0; i < 8; i++)
#pragma unroll
        for (int jj = 0; jj < 4; jj++) acc2[i][jj] = 0ull;

    int lRow = tid >> 1;
    int lCol = (tid & 1) * 4;
    const float* Aptr = A + (size_t)(block_m + lRow) * K;
    const float* Wptr = W + (size_t)lRow * K;

    const int NIT = (K + BK - 1) / BK;   // 145

    float4 av, wv;
    {   // fetch tile 0
        av = make_float4(0.f, 0.f, 0.f, 0.f);
        wv = make_float4(0.f, 0.f, 0.f, 0.f);
        if (lCol < K) {
            av = *(const float4*)(Aptr + lCol);
            wv = *(const float4*)(Wptr + lCol);
        }
        *(float2*)&As2[0][lCol + 0][2 * lRow] = make_float2(av.x, av.x);
        *(float2*)&As2[0][lCol + 1][2 * lRow] = make_float2(av.y, av.y);
        *(float2*)&As2[0][lCol + 2][2 * lRow] = make_float2(av.z, av.z);
        *(float2*)&As2[0][lCol + 3][2 * lRow] = make_float2(av.w, av.w);
        Bs[0][lCol + 0][lRow] = wv.x; Bs[0][lCol + 1][lRow] = wv.y;
        Bs[0][lCol + 2][lRow] = wv.z; Bs[0][lCol + 3][lRow] = wv.w;
    }
    __syncthreads();

    int panel_done = 0;
    float* cbase = g_cur1 + (size_t)(block_m + ty * 8) * H + tx * 8;

    for (int it = 0; it < NIT; it++) {
        int cur = it & 1;
        int nxt = cur ^ 1;

        if (it + 1 < NIT) {   // prefetch next tile while computing current
            int k0 = (it + 1) * BK;
            av = make_float4(0.f, 0.f, 0.f, 0.f);
            wv = make_float4(0.f, 0.f, 0.f, 0.f);
            if (k0 + lCol < K) {   // zero-pad tail; zeros are exact FMA no-ops
                av = *(const float4*)(Aptr + k0 + lCol);
                wv = *(const float4*)(Wptr + k0 + lCol);
            }
        }

#pragma unroll
        for (int kk = 0; kk < BK; kk++) {
            const float* arow = &As2[cur][kk][0] + ty * 16;
            const float* brow = &Bs [cur][kk][0] + tx * 8;
            ulonglong2 raA = *(const ulonglong2*)(arow);       // {a0a0},{a1a1}
            ulonglong2 raB = *(const ulonglong2*)(arow + 4);   // {a2a2},{a3a3}
            ulonglong2 raC = *(const ulonglong2*)(arow + 8);
            ulonglong2 raD = *(const ulonglong2*)(arow + 12);
            ulonglong2 rb0 = *(const ulonglong2*)(brow);       // {b0b1},{b2b3}
            ulonglong2 rb1 = *(const ulonglong2*)(brow + 4);   // {b4b5},{b6b7}
            unsigned long long ra[8] = {raA.x, raA.y, raB.x, raB.y,
                                        raC.x, raC.y, raD.x, raD.y};
            unsigned long long rb[4] = {rb0.x, rb0.y, rb1.x, rb1.y};
#pragma unroll
            for (int i = 0; i < 8; i++)
#pragma unroll
                for (int jj = 0; jj < 4; jj++)
                    acc2[i][jj] = fma2(ra[i], rb[jj], acc2[i][jj]);
        }

        if (it + 1 < NIT) {
            *(float2*)&As2[nxt][lCol + 0][2 * lRow] = make_float2(av.x, av.x);
            *(float2*)&As2[nxt][lCol + 1][2 * lRow] = make_float2(av.y, av.y);
            *(float2*)&As2[nxt][lCol + 2][2 * lRow] = make_float2(av.z, av.z);
            *(float2*)&As2[nxt][lCol + 3][2 * lRow] = make_float2(av.w, av.w);
            Bs[nxt][lCol + 0][lRow] = wv.x; Bs[nxt][lCol + 1][lRow] = wv.y;
            Bs[nxt][lCol + 2][lRow] = wv.z; Bs[nxt][lCol + 3][lRow] = wv.w;
        }
        __syncthreads();

        // Eigen panel boundary: fold partial into C (gmem), left-to-right.
        int knext = (it + 1) * BK;
        if ((knext % KC) == 0 || knext >= K) {
            if (panel_done == 0) {
#pragma unroll
                for (int i = 0; i < 8; i++) {
                    float* crow = cbase + (size_t)i * H;
                    *(ulonglong2*)(crow)     = make_ulonglong2(acc2[i][0], acc2[i][1]);
                    *(ulonglong2*)(crow + 4) = make_ulonglong2(acc2[i][2], acc2[i][3]);
                }
            } else {
#pragma unroll
                for (int i = 0; i < 8; i++) {
                    float* crow = cbase + (size_t)i * H;
                    ulonglong2 cA = *(ulonglong2*)(crow);
                    ulonglong2 cB = *(ulonglong2*)(crow + 4);
                    cA.x = add2(cA.x, acc2[i][0]);
                    cA.y = add2(cA.y, acc2[i][1]);
                    cB.x = add2(cB.x, acc2[i][2]);
                    cB.y = add2(cB.y, acc2[i][3]);
                    *(ulonglong2*)(crow)     = cA;
                    *(ulonglong2*)(crow + 4) = cB;
                }
            }
            panel_done++;
#pragma unroll
            for (int i = 0; i < 8; i++)
#pragma unroll
                for (int jj = 0; jj < 4; jj++) acc2[i][jj] = 0ull;
        }
    }
}

// ---------------------------------------------------------------------------
// Persistent LIF scan: 8 rows/block, 1024 threads, one sync per step.
// Spike sets stored as packed uchar index lists (ascending), sentinel index
// 128 points at a zeroed pad row -> fadd(+0) is a bit-exact no-op.
// Elementwise arithmetic identical to the verified version.
// ---------------------------------------------------------------------------
#define ROWS_PB 8
#define SCAN_THREADS (ROWS_PB * H)          // 1024
#define V1T_STRIDE 129
#define V1T_ELEMS (129 * 129)               // row 128 = zeros (sentinel target)
#define W2_STRIDE 129                       // col 128 = zero   (sentinel target)
#define SEG_STRIDE 36                       // 32 idx + 3 pad, 4-aligned
// floats: V1t + W2s + spk2[2][8][10] ; bytes: cnt[2][8][4] + idx[2][8][4][36]
#define SCAN_SMEM_FLOATS (V1T_ELEMS + OUT_N * W2_STRIDE + 2*ROWS_PB*OUT_N)
#define SCAN_SMEM_BYTES (SCAN_SMEM_FLOATS * 4 + 2*ROWS_PB*4 + 2*ROWS_PB*4*SEG_STRIDE)

__global__ __launch_bounds__(SCAN_THREADS, 2)
void scan_kernel(const float* __restrict__ b1, const float* __restrict__ V1,
                 const float* __restrict__ bV1, const float* __restrict__ W2,
                 const float* __restrict__ b2, const float* __restrict__ V2,
                 const float* __restrict__ bV2, float* __restrict__ out) {
    extern __shared__ float smem[];
    float* V1t   = smem;                                  // [j*129 + h], j<=128
    float* W2s   = smem + V1T_ELEMS;                      // [o*129 + j], j<=128
    float* sspk2 = W2s + OUT_N * W2_STRIDE;               // [buf][row][10]
    unsigned char* s_cnt = (unsigned char*)(sspk2 + 2 * ROWS_PB * OUT_N); // [buf][row][4]
    unsigned char* s_idx = s_cnt + 2 * ROWS_PB * 4;       // [buf][row][4][36]

    int tid = threadIdx.x;
    int h   = tid & 127;
    int r   = tid >> 7;
    int b   = blockIdx.x * ROWS_PB + r;
    int wid = tid >> 5;              // warp id; row = wid>>2, word = wid&3
    int lane = tid & 31;

    for (int idx = tid; idx < 128 * 128; idx += SCAN_THREADS) {
        int rr = idx >> 7, cc = idx & 127;
        V1t[cc * V1T_STRIDE + rr] = V1[idx];
    }
    if (tid < 129) V1t[128 * V1T_STRIDE + tid] = 0.f;     // sentinel row
    for (int idx = tid; idx < OUT_N * 128; idx += SCAN_THREADS) {
        int o = idx >> 7, j = idx & 127;
        W2s[o * W2_STRIDE + j] = W2[idx];
    }
    if (tid < OUT_N) W2s[tid * W2_STRIDE + 128] = 0.f;    // sentinel col
    if (tid < 2 * ROWS_PB * OUT_N) sspk2[tid] = 0.f;
    if (tid < 2 * ROWS_PB * 4) s_cnt[tid] = 0;

    float V2row[OUT_N];
    float b2h = 0.f, bV2h = 0.f, mem2 = 0.f;
    if (h < OUT_N) {
#pragma unroll
        for (int p = 0; p < OUT_N; p++) V2row[p] = V2[h * OUT_N + p];
        b2h = b2[h]; bV2h = bV2[h];
    }

    float b1h  = b1[h];
    float bV1h = bV1[h];
    float mem1 = 0.f;
    const float* curp = g_cur1 + (size_t)b * H + h;
    float* outbase = out + (size_t)b * OUT_N + h;
    const float* colh = V1t + h;
    __syncthreads();

    for (int t = 0; t < T_STEPS; t++) {
        int pw = t & 1;
        int pr = pw ^ 1;

        // ---- layer 1 rec: packed index lists (ascending; +0 sentinels exact) ----
        float rec1 = 0.f;
#pragma unroll
        for (int w = 0; w < 4; w++) {
            int slot = (pr * ROWS_PB + r) * 4 + w;
            int cnt = s_cnt[slot];
            const unsigned char* seg = s_idx + slot * SEG_STRIDE;
            for (int i = 0; i < cnt; i += 4) {
                unsigned p = *(const unsigned*)(seg + i);
                rec1 = __fadd_rn(rec1, colh[(p & 255u) * V1T_STRIDE]);
                rec1 = __fadd_rn(rec1, colh[((p >> 8) & 255u) * V1T_STRIDE]);
                rec1 = __fadd_rn(rec1, colh[((p >> 16) & 255u) * V1T_STRIDE]);
                rec1 = __fadd_rn(rec1, colh[(p >> 24) * V1T_STRIDE]);
            }
        }

        float gv    = curp[(size_t)t * BATCH * H];
        float cur1  = __fadd_rn(gv, b1h);
        float reset = (mem1 > 1.0f) ? 1.0f : 0.0f;
        float a     = __fmul_rn(0.9f, mem1);
        a = __fadd_rn(a, cur1);
        a = __fadd_rn(a, rec1);
        a = __fadd_rn(a, bV1h);
        mem1 = __fsub_rn(a, reset);
        float spk = (mem1 > 1.0f) ? 1.0f : 0.0f;

        // ---- expand spike mask into index list for step t (buffer pw) ----
        unsigned bal = __ballot_sync(0xffffffffu, spk != 0.0f);
        {
            int slot = (pw * ROWS_PB + (wid >> 2)) * 4 + (wid & 3);
            unsigned char* seg = s_idx + slot * SEG_STRIDE;
            if (bal & (1u << lane))
                seg[__popc(bal & ((1u << lane) - 1u))] =
                    (unsigned char)((wid & 3) * 32 + lane);
            if (lane == 0) {
                unsigned c = __popc(bal);
                s_cnt[slot] = (unsigned char)c;
                seg[c] = 128; seg[c + 1] = 128; seg[c + 2] = 128;  // sentinels
            }
        }
        __syncthreads();                 // lists(t) visible; prior-buffer reads done

        // ---- layer 2 (lanes h<10 of first warp of each row) ----
        if (h < OUT_N) {
            float c2 = 0.f;
            const float* w2 = W2s + h * W2_STRIDE;
#pragma unroll
            for (int w = 0; w < 4; w++) {
                int slot = (pw * ROWS_PB + r) * 4 + w;
                int cnt = s_cnt[slot];
                const unsigned char* seg = s_idx + slot * SEG_STRIDE;
                for (int i = 0; i < cnt; i += 4) {
                    unsigned p = *(const unsigned*)(seg + i);
                    c2 = __fadd_rn(c2, w2[p & 255u]);
                    c2 = __fadd_rn(c2, w2[(p >> 8) & 255u]);
                    c2 = __fadd_rn(c2, w2[(p >> 16) & 255u]);
                    c2 = __fadd_rn(c2, w2[p >> 24]);
                }
            }
            float cur2 = __fadd_rn(c2, b2h);
            float rec2 = 0.f;
            const float* sp_prev = sspk2 + (pr * ROWS_PB + r) * OUT_N;
#pragma unroll
            for (int p = 0; p < OUT_N; p++) {
                if (sp_prev[p] != 0.0f) rec2 = __fadd_rn(rec2, V2row[p]);
            }
            float reset2 = (mem2 > 1.0f) ? 1.0f : 0.0f;
            float u = __fmul_rn(0.9f, mem2);
            u = __fadd_rn(u, cur2);
            u = __fadd_rn(u, rec2);
            u = __fadd_rn(u, bV2h);
            mem2 = __fsub_rn(u, reset2);
            float s2 = (mem2 > 1.0f) ? 1.0f : 0.0f;
            outbase[(size_t)t * BATCH * OUT_N] = s2;
            sspk2[(pw * ROWS_PB + r) * OUT_N + h] = s2;
        }
        // next iteration's __syncthreads orders these writes vs reads at t+1
    }
}

extern "C" void kernel_launch(void* const* d_in, const int* in_sizes, int n_in,
                              void* d_out, int out_size) {
    const float* x   = (const float*)d_in[0];
    const float* W1  = (const float*)d_in[1];
    const float* b1  = (const float*)d_in[2];
    const float* V1  = (const float*)d_in[3];
    const float* bV1 = (const float*)d_in[4];
    const float* W2  = (const float*)d_in[5];
    const float* b2  = (const float*)d_in[6];
    const float* V2  = (const float*)d_in[7];
    const float* bV2 = (const float*)d_in[8];
    float* out = (float*)d_out;

    cudaFuncSetAttribute(scan_kernel, cudaFuncAttributeMaxDynamicSharedMemorySize,
                         SCAN_SMEM_BYTES);

    const int M = T_STEPS * BATCH;  // 102400
    gemm_xw1<<<M / 128, 256>>>(x, W1, M, D_IN);
    scan_kernel<<<BATCH / ROWS_PB, SCAN_THREADS, SCAN_SMEM_BYTES>>>(
        b1, V1, bV1, W2, b2, V2, bV2, out);
}

// round 8
// speedup vs baseline: 1.1399x; 1.1399x over previous
#include <cuda_runtime.h>

#define T_STEPS 50
#define BATCH   2048
#define D_IN    1156
#define H       128
#define OUT_N   10
#define KC      248          // Eigen kc (aarch64 default l1=16KB) -- verified exact

// Scratch: cur1[t][b][h] = (x[t,b,:] @ W1.T)[h]   (bias b1 added in scan)
__device__ float g_cur1[(size_t)T_STEPS * BATCH * H];  // 52.4 MB

// ---------------------------------------------------------------------------
// SGEMM emulating Eigen gebp (bit-exact, verified R4/R6): KC=248 panels, each
// an ascending-k FMA chain per element, folded left-to-right in GMEM.
// 128x128 tile, BK=8, 256 threads, 8x8 micro-tile, double-buffered smem,
// single accumulator set -> 2 blocks/SM. Measured 840us (FFMA issue floor).
// ---------------------------------------------------------------------------
__global__ __launch_bounds__(256, 2)
void gemm_xw1(const float* __restrict__ A, const float* __restrict__ W, int M, int K) {
    const int BK = 8;
    __shared__ float As[2][BK][128];
    __shared__ float Bs[2][BK][128];

    int tid = threadIdx.x;
    int block_m = blockIdx.x * 128;
    int tx = tid & 15;
    int ty = tid >> 4;

    float acc[8][8];
#pragma unroll
    for (int i = 0; i < 8; i++)
#pragma unroll
        for (int j = 0; j < 8; j++) acc[i][j] = 0.f;

    int lRow = tid >> 1;
    int lCol = (tid & 1) * 4;
    const float* Aptr = A + (size_t)(block_m + lRow) * K;
    const float* Wptr = W + (size_t)lRow * K;

    const int NIT = (K + BK - 1) / BK;   // 145

    float4 av, wv;
    {   // fetch tile 0
        av = make_float4(0.f, 0.f, 0.f, 0.f);
        wv = make_float4(0.f, 0.f, 0.f, 0.f);
        if (lCol < K) {
            av = *(const float4*)(Aptr + lCol);
            wv = *(const float4*)(Wptr + lCol);
        }
        As[0][lCol + 0][lRow] = av.x; As[0][lCol + 1][lRow] = av.y;
        As[0][lCol + 2][lRow] = av.z; As[0][lCol + 3][lRow] = av.w;
        Bs[0][lCol + 0][lRow] = wv.x; Bs[0][lCol + 1][lRow] = wv.y;
        Bs[0][lCol + 2][lRow] = wv.z; Bs[0][lCol + 3][lRow] = wv.w;
    }
    __syncthreads();

    int panel_done = 0;
    float* cbase = g_cur1 + (size_t)(block_m + ty * 8) * H + tx * 8;

    for (int it = 0; it < NIT; it++) {
        int cur = it & 1;
        int nxt = cur ^ 1;

        if (it + 1 < NIT) {   // prefetch next tile while computing current
            int k0 = (it + 1) * BK;
            av = make_float4(0.f, 0.f, 0.f, 0.f);
            wv = make_float4(0.f, 0.f, 0.f, 0.f);
            if (k0 + lCol < K) {   // zero-pad tail; zeros are exact FMA no-ops
                av = *(const float4*)(Aptr + k0 + lCol);
                wv = *(const float4*)(Wptr + k0 + lCol);
            }
        }

#pragma unroll
        for (int kk = 0; kk < BK; kk++) {
            float ra[8], rb[8];
#pragma unroll
            for (int i = 0; i < 8; i++) ra[i] = As[cur][kk][ty * 8 + i];
#pragma unroll
            for (int j = 0; j < 8; j++) rb[j] = Bs[cur][kk][tx * 8 + j];
#pragma unroll
            for (int i = 0; i < 8; i++)
#pragma unroll
                for (int j = 0; j < 8; j++)
                    acc[i][j] = __fmaf_rn(ra[i], rb[j], acc[i][j]);
        }

        if (it + 1 < NIT) {
            As[nxt][lCol + 0][lRow] = av.x; As[nxt][lCol + 1][lRow] = av.y;
            As[nxt][lCol + 2][lRow] = av.z; As[nxt][lCol + 3][lRow] = av.w;
            Bs[nxt][lCol + 0][lRow] = wv.x; Bs[nxt][lCol + 1][lRow] = wv.y;
            Bs[nxt][lCol + 2][lRow] = wv.z; Bs[nxt][lCol + 3][lRow] = wv.w;
        }
        __syncthreads();

        // Eigen panel boundary: fold partial into C (gmem), left-to-right.
        int knext = (it + 1) * BK;
        if ((knext % KC) == 0 || knext >= K) {
            if (panel_done == 0) {
#pragma unroll
                for (int i = 0; i < 8; i++) {
                    float* crow = cbase + (size_t)i * H;
#pragma unroll
                    for (int j = 0; j < 8; j += 4)
                        *(float4*)(crow + j) = make_float4(acc[i][j], acc[i][j+1],
                                                           acc[i][j+2], acc[i][j+3]);
                }
            } else {
#pragma unroll
                for (int i = 0; i < 8; i++) {
                    float* crow = cbase + (size_t)i * H;
#pragma unroll
                    for (int j = 0; j < 8; j += 4) {
                        float4 c = *(float4*)(crow + j);
                        c.x = __fadd_rn(c.x, acc[i][j    ]);
                        c.y = __fadd_rn(c.y, acc[i][j + 1]);
                        c.z = __fadd_rn(c.z, acc[i][j + 2]);
                        c.w = __fadd_rn(c.w, acc[i][j + 3]);
                        *(float4*)(crow + j) = c;
                    }
                }
            }
            panel_done++;
#pragma unroll
            for (int i = 0; i < 8; i++)
#pragma unroll
                for (int j = 0; j < 8; j++) acc[i][j] = 0.f;
        }
    }
}

// ---------------------------------------------------------------------------
// Persistent LIF scan: 8 rows/block, 512 threads, TWO rows per thread
// (independent chains -> 2x ILP), per-row-group NAMED barriers (128 threads)
// so rows advance independently. Double-buffered masks/spk2 -> one barrier
// per step. Elementwise arithmetic identical to the verified R4/R6 version.
// ---------------------------------------------------------------------------
#define ROWS_PB 8
#define SCAN_THREADS 512
#define V1T_STRIDE 129
#define V1T_ELEMS (128 * V1T_STRIDE)
#define W2_STRIDE 129
#define SCAN_SMEM_FLOATS (V1T_ELEMS + OUT_N * W2_STRIDE + 2*ROWS_PB*OUT_N + 2*ROWS_PB*4)
#define SCAN_SMEM_BYTES (SCAN_SMEM_FLOATS * 4)

__global__ __launch_bounds__(SCAN_THREADS, 2)
void scan_kernel(const float* __restrict__ b1, const float* __restrict__ V1,
                 const float* __restrict__ bV1, const float* __restrict__ W2,
                 const float* __restrict__ b2, const float* __restrict__ V2,
                 const float* __restrict__ bV2, float* __restrict__ out) {
    extern __shared__ float smem[];
    float* V1t   = smem;                                  // [j*129 + h] = V1[h][j]
    float* W2s   = smem + V1T_ELEMS;                      // [o*129 + j]
    float* sspk2 = W2s + OUT_N * W2_STRIDE;               // [buf][row][10]
    unsigned* s_mask = (unsigned*)(sspk2 + 2 * ROWS_PB * OUT_N); // [buf][row][4]

    int tid  = threadIdx.x;
    int h    = tid & 127;
    int q    = tid >> 7;             // row group 0..3; thread owns rows q and q+4
    int rA   = q;
    int rB   = q + 4;
    int bA   = blockIdx.x * ROWS_PB + rA;
    int bB   = blockIdx.x * ROWS_PB + rB;
    int wid  = tid >> 5;             // warp 0..15; group = wid>>2, word = wid&3
    int word = wid & 3;

    for (int idx = tid; idx < 128 * 128; idx += SCAN_THREADS) {
        int rr = idx >> 7, cc = idx & 127;
        V1t[cc * V1T_STRIDE + rr] = V1[idx];
    }
    for (int idx = tid; idx < OUT_N * 128; idx += SCAN_THREADS) {
        int o = idx >> 7, j = idx & 127;
        W2s[o * W2_STRIDE + j] = W2[idx];
    }
    if (tid < 2 * ROWS_PB * OUT_N) sspk2[tid] = 0.f;
    if (tid < 2 * ROWS_PB * 4) s_mask[tid] = 0u;

    float V2row[OUT_N];
    float b2h = 0.f, bV2h = 0.f, mem2A = 0.f, mem2B = 0.f;
    if (h < OUT_N) {
#pragma unroll
        for (int p = 0; p < OUT_N; p++) V2row[p] = V2[h * OUT_N + p];
        b2h = b2[h]; bV2h = bV2[h];
    }

    float b1h  = b1[h];
    float bV1h = bV1[h];
    float mem1A = 0.f, mem1B = 0.f;
    const float* curA = g_cur1 + (size_t)bA * H + h;
    const float* curB = g_cur1 + (size_t)bB * H + h;
    float* outA = out + (size_t)bA * OUT_N + h;
    float* outB = out + (size_t)bB * OUT_N + h;
    const float* colh = V1t + h;
    __syncthreads();                 // V1t/W2s/init visible to all

    for (int t = 0; t < T_STEPS; t++) {
        int pw = t & 1;
        int pr = pw ^ 1;

        // ---- layer 1 rec terms for both rows (independent chains) ----
        float recA = 0.f, recB = 0.f;
#pragma unroll
        for (int w = 0; w < 4; w++) {
            unsigned mA = s_mask[(pr * ROWS_PB + rA) * 4 + w];
            unsigned mB = s_mask[(pr * ROWS_PB + rB) * 4 + w];
            const float* base = colh + (w * 32) * V1T_STRIDE;
            while (mA) {
                int j = __ffs(mA) - 1; mA &= mA - 1;
                recA = __fadd_rn(recA, base[j * V1T_STRIDE]);
            }
            while (mB) {
                int j = __ffs(mB) - 1; mB &= mB - 1;
                recB = __fadd_rn(recB, base[j * V1T_STRIDE]);
            }
        }

        float gvA = curA[(size_t)t * BATCH * H];
        float gvB = curB[(size_t)t * BATCH * H];

        float aA = __fmul_rn(0.9f, mem1A);
        aA = __fadd_rn(aA, __fadd_rn(gvA, b1h));
        aA = __fadd_rn(aA, recA);
        aA = __fadd_rn(aA, bV1h);
        float resetA = (mem1A > 1.0f) ? 1.0f : 0.0f;
        mem1A = __fsub_rn(aA, resetA);
        float spkA = (mem1A > 1.0f) ? 1.0f : 0.0f;

        float aB = __fmul_rn(0.9f, mem1B);
        aB = __fadd_rn(aB, __fadd_rn(gvB, b1h));
        aB = __fadd_rn(aB, recB);
        aB = __fadd_rn(aB, bV1h);
        float resetB = (mem1B > 1.0f) ? 1.0f : 0.0f;
        mem1B = __fsub_rn(aB, resetB);
        float spkB = (mem1B > 1.0f) ? 1.0f : 0.0f;

        unsigned balA = __ballot_sync(0xffffffffu, spkA != 0.0f);
        unsigned balB = __ballot_sync(0xffffffffu, spkB != 0.0f);
        if ((tid & 31) == 0) {
            s_mask[(pw * ROWS_PB + rA) * 4 + word] = balA;
            s_mask[(pw * ROWS_PB + rB) * 4 + word] = balB;
        }
        // per-row-group barrier: syncs the 4 warps (128 threads) of group q
        asm volatile("bar.sync %0, 128;" :: "r"(1 + q) : "memory");

        // ---- layer 2 for both rows (lanes h<10 of first warp of group) ----
        if (h < OUT_N) {
            const float* w2 = W2s + h * W2_STRIDE;
            float c2A = 0.f, c2B = 0.f;
#pragma unroll
            for (int w = 0; w < 4; w++) {
                unsigned nA = s_mask[(pw * ROWS_PB + rA) * 4 + w];
                unsigned nB = s_mask[(pw * ROWS_PB + rB) * 4 + w];
                const float* base = w2 + w * 32;
                while (nA) {
                    int j = __ffs(nA) - 1; nA &= nA - 1;
                    c2A = __fadd_rn(c2A, base[j]);
                }
                while (nB) {
                    int j = __ffs(nB) - 1; nB &= nB - 1;
                    c2B = __fadd_rn(c2B, base[j]);
                }
            }
            float rec2A = 0.f, rec2B = 0.f;
            const float* spA = sspk2 + (pr * ROWS_PB + rA) * OUT_N;
            const float* spB = sspk2 + (pr * ROWS_PB + rB) * OUT_N;
#pragma unroll
            for (int p = 0; p < OUT_N; p++) {
                if (spA[p] != 0.0f) rec2A = __fadd_rn(rec2A, V2row[p]);
                if (spB[p] != 0.0f) rec2B = __fadd_rn(rec2B, V2row[p]);
            }
            float uA = __fmul_rn(0.9f, mem2A);
            uA = __fadd_rn(uA, __fadd_rn(c2A, b2h));
            uA = __fadd_rn(uA, rec2A);
            uA = __fadd_rn(uA, bV2h);
            float reset2A = (mem2A > 1.0f) ? 1.0f : 0.0f;
            mem2A = __fsub_rn(uA, reset2A);
            float s2A = (mem2A > 1.0f) ? 1.0f : 0.0f;

            float uB = __fmul_rn(0.9f, mem2B);
            uB = __fadd_rn(uB, __fadd_rn(c2B, b2h));
            uB = __fadd_rn(uB, rec2B);
            uB = __fadd_rn(uB, bV2h);
            float reset2B = (mem2B > 1.0f) ? 1.0f : 0.0f;
            mem2B = __fsub_rn(uB, reset2B);
            float s2B = (mem2B > 1.0f) ? 1.0f : 0.0f;

            outA[(size_t)t * BATCH * OUT_N] = s2A;
            outB[(size_t)t * BATCH * OUT_N] = s2B;
            sspk2[(pw * ROWS_PB + rA) * OUT_N + h] = s2A;
            sspk2[(pw * ROWS_PB + rB) * OUT_N + h] = s2B;
        }
        // next step's group barrier orders these writes vs reads at t+1
    }
}

extern "C" void kernel_launch(void* const* d_in, const int* in_sizes, int n_in,
                              void* d_out, int out_size) {
    const float* x   = (const float*)d_in[0];
    const float* W1  = (const float*)d_in[1];
    const float* b1  = (const float*)d_in[2];
    const float* V1  = (const float*)d_in[3];
    const float* bV1 = (const float*)d_in[4];
    const float* W2  = (const float*)d_in[5];
    const float* b2  = (const float*)d_in[6];
    const float* V2  = (const float*)d_in[7];
    const float* bV2 = (const float*)d_in[8];
    float* out = (float*)d_out;

    cudaFuncSetAttribute(scan_kernel, cudaFuncAttributeMaxDynamicSharedMemorySize,
                         SCAN_SMEM_BYTES);

    const int M = T_STEPS * BATCH;  // 102400
    gemm_xw1<<<M / 128, 256>>>(x, W1, M, D_IN);
    scan_kernel<<<BATCH / ROWS_PB, SCAN_THREADS, SCAN_SMEM_BYTES>>>(
        b1, V1, bV1, W2, b2, V2, bV2, out);
}

// round 9
// speedup vs baseline: 1.1563x; 1.0143x over previous
#include <cuda_runtime.h>

#define T_STEPS 50
#define BATCH   2048
#define D_IN    1156
#define H       128
#define OUT_N   10
#define KC      248          // Eigen kc (aarch64 default l1=16KB) -- verified exact

// Scratch: cur1[t][b][h] = (x[t,b,:] @ W1.T)[h]   (bias b1 added in scan)
__device__ float g_cur1[(size_t)T_STEPS * BATCH * H];  // 52.4 MB
// Per-timestep completion counters (16 GEMM tiles per timestep)
__device__ int g_cnt[T_STEPS];

__device__ __forceinline__ int ld_acquire_gpu(const int* p) {
    int v;
    asm volatile("ld.acquire.gpu.b32 %0, [%1];" : "=r"(v) : "l"(p) : "memory");
    return v;
}

// ---------------------------------------------------------------------------
// SGEMM emulating Eigen gebp (bit-exact, verified): KC=248 panels, each an
// ascending-k FMA chain per element, folded left-to-right in GMEM.
// 128x128 tile, BK=8, 256 threads, 8x8 micro-tile, double-buffered smem,
// 2 blocks/SM. After the final fold, signals tile completion via g_cnt[t].
// ---------------------------------------------------------------------------
__global__ __launch_bounds__(256, 2)
void gemm_xw1(const float* __restrict__ A, const float* __restrict__ W, int M, int K) {
    const int BK = 8;
    __shared__ float As[2][BK][128];
    __shared__ float Bs[2][BK][128];

    int tid = threadIdx.x;
    int block_m = blockIdx.x * 128;
    int tx = tid & 15;
    int ty = tid >> 4;

    float acc[8][8];
#pragma unroll
    for (int i = 0; i < 8; i++)
#pragma unroll
        for (int j = 0; j < 8; j++) acc[i][j] = 0.f;

    int lRow = tid >> 1;
    int lCol = (tid & 1) * 4;
    const float* Aptr = A + (size_t)(block_m + lRow) * K;
    const float* Wptr = W + (size_t)lRow * K;

    const int NIT = (K + BK - 1) / BK;   // 145

    float4 av, wv;
    {   // fetch tile 0
        av = make_float4(0.f, 0.f, 0.f, 0.f);
        wv = make_float4(0.f, 0.f, 0.f, 0.f);
        if (lCol < K) {
            av = *(const float4*)(Aptr + lCol);
            wv = *(const float4*)(Wptr + lCol);
        }
        As[0][lCol + 0][lRow] = av.x; As[0][lCol + 1][lRow] = av.y;
        As[0][lCol + 2][lRow] = av.z; As[0][lCol + 3][lRow] = av.w;
        Bs[0][lCol + 0][lRow] = wv.x; Bs[0][lCol + 1][lRow] = wv.y;
        Bs[0][lCol + 2][lRow] = wv.z; Bs[0][lCol + 3][lRow] = wv.w;
    }
    __syncthreads();

    int panel_done = 0;
    float* cbase = g_cur1 + (size_t)(block_m + ty * 8) * H + tx * 8;

    for (int it = 0; it < NIT; it++) {
        int cur = it & 1;
        int nxt = cur ^ 1;

        if (it + 1 < NIT) {   // prefetch next tile while computing current
            int k0 = (it + 1) * BK;
            av = make_float4(0.f, 0.f, 0.f, 0.f);
            wv = make_float4(0.f, 0.f, 0.f, 0.f);
            if (k0 + lCol < K) {   // zero-pad tail; zeros are exact FMA no-ops
                av = *(const float4*)(Aptr + k0 + lCol);
                wv = *(const float4*)(Wptr + k0 + lCol);
            }
        }

#pragma unroll
        for (int kk = 0; kk < BK; kk++) {
            float ra[8], rb[8];
#pragma unroll
            for (int i = 0; i < 8; i++) ra[i] = As[cur][kk][ty * 8 + i];
#pragma unroll
            for (int j = 0; j < 8; j++) rb[j] = Bs[cur][kk][tx * 8 + j];
#pragma unroll
            for (int i = 0; i < 8; i++)
#pragma unroll
                for (int j = 0; j < 8; j++)
                    acc[i][j] = __fmaf_rn(ra[i], rb[j], acc[i][j]);
        }

        if (it + 1 < NIT) {
            As[nxt][lCol + 0][lRow] = av.x; As[nxt][lCol + 1][lRow] = av.y;
            As[nxt][lCol + 2][lRow] = av.z; As[nxt][lCol + 3][lRow] = av.w;
            Bs[nxt][lCol + 0][lRow] = wv.x; Bs[nxt][lCol + 1][lRow] = wv.y;
            Bs[nxt][lCol + 2][lRow] = wv.z; Bs[nxt][lCol + 3][lRow] = wv.w;
        }
        __syncthreads();

        // Eigen panel boundary: fold partial into C (gmem), left-to-right.
        int knext = (it + 1) * BK;
        if ((knext % KC) == 0 || knext >= K) {
            if (panel_done == 0) {
#pragma unroll
                for (int i = 0; i < 8; i++) {
                    float* crow = cbase + (size_t)i * H;
#pragma unroll
                    for (int j = 0; j < 8; j += 4)
                        *(float4*)(crow + j) = make_float4(acc[i][j], acc[i][j+1],
                                                           acc[i][j+2], acc[i][j+3]);
                }
            } else {
#pragma unroll
                for (int i = 0; i < 8; i++) {
                    float* crow = cbase + (size_t)i * H;
#pragma unroll
                    for (int j = 0; j < 8; j += 4) {
                        float4 c = *(float4*)(crow + j);
                        c.x = __fadd_rn(c.x, acc[i][j    ]);
                        c.y = __fadd_rn(c.y, acc[i][j + 1]);
                        c.z = __fadd_rn(c.z, acc[i][j + 2]);
                        c.w = __fadd_rn(c.w, acc[i][j + 3]);
                        *(float4*)(crow + j) = c;
                    }
                }
            }
            panel_done++;
#pragma unroll
            for (int i = 0; i < 8; i++)
#pragma unroll
                for (int j = 0; j < 8; j++) acc[i][j] = 0.f;
        }
    }

    // Signal: this tile (128 M-rows, all within one timestep) is complete.
    __threadfence();
    __syncthreads();
    if (tid == 0) atomicAdd(&g_cnt[block_m >> 11], 1);   // 2048 rows per t
}

// ---------------------------------------------------------------------------
// Persistent LIF scan (R8 structure, verified): 8 rows/block, 512 threads,
// two rows per thread, per-row-group named barriers, double-buffered state.
// Adds a per-timestep acquire-poll on g_cnt[t] so it can run concurrently
// with (the tail of) the GEMM.
// ---------------------------------------------------------------------------
#define ROWS_PB 8
#define SCAN_THREADS 512
#define V1T_STRIDE 129
#define V1T_ELEMS (128 * V1T_STRIDE)
#define W2_STRIDE 129
#define SCAN_SMEM_FLOATS (V1T_ELEMS + OUT_N * W2_STRIDE + 2*ROWS_PB*OUT_N + 2*ROWS_PB*4)
#define SCAN_SMEM_BYTES (SCAN_SMEM_FLOATS * 4)

__global__ __launch_bounds__(SCAN_THREADS, 2)
void scan_kernel(const float* __restrict__ b1, const float* __restrict__ V1,
                 const float* __restrict__ bV1, const float* __restrict__ W2,
                 const float* __restrict__ b2, const float* __restrict__ V2,
                 const float* __restrict__ bV2, float* __restrict__ out) {
    extern __shared__ float smem[];
    float* V1t   = smem;                                  // [j*129 + h] = V1[h][j]
    float* W2s   = smem + V1T_ELEMS;                      // [o*129 + j]
    float* sspk2 = W2s + OUT_N * W2_STRIDE;               // [buf][row][10]
    unsigned* s_mask = (unsigned*)(sspk2 + 2 * ROWS_PB * OUT_N); // [buf][row][4]

    int tid  = threadIdx.x;
    int h    = tid & 127;
    int q    = tid >> 7;             // row group 0..3; thread owns rows q and q+4
    int rA   = q;
    int rB   = q + 4;
    int bA   = blockIdx.x * ROWS_PB + rA;
    int bB   = blockIdx.x * ROWS_PB + rB;
    int wid  = tid >> 5;             // warp 0..15; group = wid>>2, word = wid&3
    int word = wid & 3;

    for (int idx = tid; idx < 128 * 128; idx += SCAN_THREADS) {
        int rr = idx >> 7, cc = idx & 127;
        V1t[cc * V1T_STRIDE + rr] = V1[idx];
    }
    for (int idx = tid; idx < OUT_N * 128; idx += SCAN_THREADS) {
        int o = idx >> 7, j = idx & 127;
        W2s[o * W2_STRIDE + j] = W2[idx];
    }
    if (tid < 2 * ROWS_PB * OUT_N) sspk2[tid] = 0.f;
    if (tid < 2 * ROWS_PB * 4) s_mask[tid] = 0u;

    float V2row[OUT_N];
    float b2h = 0.f, bV2h = 0.f, mem2A = 0.f, mem2B = 0.f;
    if (h < OUT_N) {
#pragma unroll
        for (int p = 0; p < OUT_N; p++) V2row[p] = V2[h * OUT_N + p];
        b2h = b2[h]; bV2h = bV2[h];
    }

    float b1h  = b1[h];
    float bV1h = bV1[h];
    float mem1A = 0.f, mem1B = 0.f;
    const float* curA = g_cur1 + (size_t)bA * H + h;
    const float* curB = g_cur1 + (size_t)bB * H + h;
    float* outA = out + (size_t)bA * OUT_N + h;
    float* outB = out + (size_t)bB * OUT_N + h;
    const float* colh = V1t + h;
    __syncthreads();                 // V1t/W2s/init visible to all

    for (int t = 0; t < T_STEPS; t++) {
        int pw = t & 1;
        int pr = pw ^ 1;

        // Wait until all 16 GEMM tiles for timestep t are complete.
        while (ld_acquire_gpu(&g_cnt[t]) < 16) __nanosleep(200);

        // ---- layer 1 rec terms for both rows (independent chains) ----
        float recA = 0.f, recB = 0.f;
#pragma unroll
        for (int w = 0; w < 4; w++) {
            unsigned mA = s_mask[(pr * ROWS_PB + rA) * 4 + w];
            unsigned mB = s_mask[(pr * ROWS_PB + rB) * 4 + w];
            const float* base = colh + (w * 32) * V1T_STRIDE;
            while (mA) {
                int j = __ffs(mA) - 1; mA &= mA - 1;
                recA = __fadd_rn(recA, base[j * V1T_STRIDE]);
            }
            while (mB) {
                int j = __ffs(mB) - 1; mB &= mB - 1;
                recB = __fadd_rn(recB, base[j * V1T_STRIDE]);
            }
        }

        float gvA = curA[(size_t)t * BATCH * H];
        float gvB = curB[(size_t)t * BATCH * H];

        float aA = __fmul_rn(0.9f, mem1A);
        aA = __fadd_rn(aA, __fadd_rn(gvA, b1h));
        aA = __fadd_rn(aA, recA);
        aA = __fadd_rn(aA, bV1h);
        float resetA = (mem1A > 1.0f) ? 1.0f : 0.0f;
        mem1A = __fsub_rn(aA, resetA);
        float spkA = (mem1A > 1.0f) ? 1.0f : 0.0f;

        float aB = __fmul_rn(0.9f, mem1B);
        aB = __fadd_rn(aB, __fadd_rn(gvB, b1h));
        aB = __fadd_rn(aB, recB);
        aB = __fadd_rn(aB, bV1h);
        float resetB = (mem1B > 1.0f) ? 1.0f : 0.0f;
        mem1B = __fsub_rn(aB, resetB);
        float spkB = (mem1B > 1.0f) ? 1.0f : 0.0f;

        unsigned balA = __ballot_sync(0xffffffffu, spkA != 0.0f);
        unsigned balB = __ballot_sync(0xffffffffu, spkB != 0.0f);
        if ((tid & 31) == 0) {
            s_mask[(pw * ROWS_PB + rA) * 4 + word] = balA;
            s_mask[(pw * ROWS_PB + rB) * 4 + word] = balB;
        }
        // per-row-group barrier: syncs the 4 warps (128 threads) of group q
        asm volatile("bar.sync %0, 128;" :: "r"(1 + q) : "memory");

        // ---- layer 2 for both rows (lanes h<10 of first warp of group) ----
        if (h < OUT_N) {
            const float* w2 = W2s + h * W2_STRIDE;
            float c2A = 0.f, c2B = 0.f;
#pragma unroll
            for (int w = 0; w < 4; w++) {
                unsigned nA = s_mask[(pw * ROWS_PB + rA) * 4 + w];
                unsigned nB = s_mask[(pw * ROWS_PB + rB) * 4 + w];
                const float* base = w2 + w * 32;
                while (nA) {
                    int j = __ffs(nA) - 1; nA &= nA - 1;
                    c2A = __fadd_rn(c2A, base[j]);
                }
                while (nB) {
                    int j = __ffs(nB) - 1; nB &= nB - 1;
                    c2B = __fadd_rn(c2B, base[j]);
                }
            }
            float rec2A = 0.f, rec2B = 0.f;
            const float* spA = sspk2 + (pr * ROWS_PB + rA) * OUT_N;
            const float* spB = sspk2 + (pr * ROWS_PB + rB) * OUT_N;
#pragma unroll
            for (int p = 0; p < OUT_N; p++) {
                if (spA[p] != 0.0f) rec2A = __fadd_rn(rec2A, V2row[p]);
                if (spB[p] != 0.0f) rec2B = __fadd_rn(rec2B, V2row[p]);
            }
            float uA = __fmul_rn(0.9f, mem2A);
            uA = __fadd_rn(uA, __fadd_rn(c2A, b2h));
            uA = __fadd_rn(uA, rec2A);
            uA = __fadd_rn(uA, bV2h);
            float reset2A = (mem2A > 1.0f) ? 1.0f : 0.0f;
            mem2A = __fsub_rn(uA, reset2A);
            float s2A = (mem2A > 1.0f) ? 1.0f : 0.0f;

            float uB = __fmul_rn(0.9f, mem2B);
            uB = __fadd_rn(uB, __fadd_rn(c2B, b2h));
            uB = __fadd_rn(uB, rec2B);
            uB = __fadd_rn(uB, bV2h);
            float reset2B = (mem2B > 1.0f) ? 1.0f : 0.0f;
            mem2B = __fsub_rn(uB, reset2B);
            float s2B = (mem2B > 1.0f) ? 1.0f : 0.0f;

            outA[(size_t)t * BATCH * OUT_N] = s2A;
            outB[(size_t)t * BATCH * OUT_N] = s2B;
            sspk2[(pw * ROWS_PB + rA) * OUT_N + h] = s2A;
            sspk2[(pw * ROWS_PB + rB) * OUT_N + h] = s2B;
        }
        // next step's group barrier orders these writes vs reads at t+1
    }
}

extern "C" void kernel_launch(void* const* d_in, const int* in_sizes, int n_in,
                              void* d_out, int out_size) {
    const float* x   = (const float*)d_in[0];
    const float* W1  = (const float*)d_in[1];
    const float* b1  = (const float*)d_in[2];
    const float* V1  = (const float*)d_in[3];
    const float* bV1 = (const float*)d_in[4];
    const float* W2  = (const float*)d_in[5];
    const float* b2  = (const float*)d_in[6];
    const float* V2  = (const float*)d_in[7];
    const float* bV2 = (const float*)d_in[8];
    float* out = (float*)d_out;

    cudaFuncSetAttribute(scan_kernel, cudaFuncAttributeMaxDynamicSharedMemorySize,
                         SCAN_SMEM_BYTES);

    // Zero the per-timestep completion counters (captured async memset).
    void* cnt_addr = nullptr;
    cudaGetSymbolAddress(&cnt_addr, g_cnt);
    cudaMemsetAsync(cnt_addr, 0, T_STEPS * sizeof(int), 0);

    // Fork a side stream for the scan so it can overlap the GEMM tail.
    cudaStream_t s2;
    cudaStreamCreateWithFlags(&s2, cudaStreamNonBlocking);
    cudaEvent_t eF, eJ;
    cudaEventCreateWithFlags(&eF, cudaEventDisableTiming);
    cudaEventCreateWithFlags(&eJ, cudaEventDisableTiming);

    cudaEventRecord(eF, 0);           // after memset on the capture stream
    cudaStreamWaitEvent(s2, eF, 0);

    const int M = T_STEPS * BATCH;    // 102400
    // GEMM launched FIRST: its 800 blocks are dispatched ahead of the scan's
    // (FIFO), so the scan can never starve the GEMM -> no deadlock.
    gemm_xw1<<<M / 128, 256, 0, 0>>>(x, W1, M, D_IN);
    scan_kernel<<<BATCH / ROWS_PB, SCAN_THREADS, SCAN_SMEM_BYTES, s2>>>(
        b1, V1, bV1, W2, b2, V2, bV2, out);

    cudaEventRecord(eJ, s2);          // join scan back into the capture stream
    cudaStreamWaitEvent(0, eJ, 0);

    cudaEventDestroy(eF);
    cudaEventDestroy(eJ);
    cudaStreamDestroy(s2);
}

// round 10
// speedup vs baseline: 1.1577x; 1.0012x over previous
#include <cuda_runtime.h>

#define T_STEPS 50
#define BATCH   2048
#define D_IN    1156
#define H       128
#define OUT_N   10
#define KC      248          // Eigen kc (aarch64 default l1=16KB) -- verified exact

// Scratch: cur1[t][b][h] = (x[t,b,:] @ W1.T)[h]   (bias b1 added in scan)
__device__ float g_cur1[(size_t)T_STEPS * BATCH * H];  // 52.4 MB
// Per-timestep completion counters (16 GEMM tiles per timestep)
__device__ int g_cnt[T_STEPS];

__device__ __forceinline__ int ld_acquire_gpu(const int* p) {
    int v;
    asm volatile("ld.acquire.gpu.b32 %0, [%1];" : "=r"(v) : "l"(p) : "memory");
    return v;
}

// ---------------------------------------------------------------------------
// SGEMM emulating Eigen gebp (bit-exact, verified): KC=248 panels, each an
// ascending-k FMA chain per element, folded left-to-right in GMEM.
// 128x128 tile, BK=8, 256 threads, 8x8 micro-tile, double-buffered smem,
// 2 blocks/SM. After the final fold, signals tile completion via g_cnt[t].
// ---------------------------------------------------------------------------
__global__ __launch_bounds__(256, 2)
void gemm_xw1(const float* __restrict__ A, const float* __restrict__ W, int M, int K) {
    const int BK = 8;
    __shared__ float As[2][BK][128];
    __shared__ float Bs[2][BK][128];

    int tid = threadIdx.x;
    int block_m = blockIdx.x * 128;
    int tx = tid & 15;
    int ty = tid >> 4;

    float acc[8][8];
#pragma unroll
    for (int i = 0; i < 8; i++)
#pragma unroll
        for (int j = 0; j < 8; j++) acc[i][j] = 0.f;

    int lRow = tid >> 1;
    int lCol = (tid & 1) * 4;
    const float* Aptr = A + (size_t)(block_m + lRow) * K;
    const float* Wptr = W + (size_t)lRow * K;

    const int NIT = (K + BK - 1) / BK;   // 145

    float4 av, wv;
    {   // fetch tile 0
        av = make_float4(0.f, 0.f, 0.f, 0.f);
        wv = make_float4(0.f, 0.f, 0.f, 0.f);
        if (lCol < K) {
            av = *(const float4*)(Aptr + lCol);
            wv = *(const float4*)(Wptr + lCol);
        }
        As[0][lCol + 0][lRow] = av.x; As[0][lCol + 1][lRow] = av.y;
        As[0][lCol + 2][lRow] = av.z; As[0][lCol + 3][lRow] = av.w;
        Bs[0][lCol + 0][lRow] = wv.x; Bs[0][lCol + 1][lRow] = wv.y;
        Bs[0][lCol + 2][lRow] = wv.z; Bs[0][lCol + 3][lRow] = wv.w;
    }
    __syncthreads();

    int panel_done = 0;
    float* cbase = g_cur1 + (size_t)(block_m + ty * 8) * H + tx * 8;

    for (int it = 0; it < NIT; it++) {
        int cur = it & 1;
        int nxt = cur ^ 1;

        if (it + 1 < NIT) {   // prefetch next tile while computing current
            int k0 = (it + 1) * BK;
            av = make_float4(0.f, 0.f, 0.f, 0.f);
            wv = make_float4(0.f, 0.f, 0.f, 0.f);
            if (k0 + lCol < K) {   // zero-pad tail; zeros are exact FMA no-ops
                av = *(const float4*)(Aptr + k0 + lCol);
                wv = *(const float4*)(Wptr + k0 + lCol);
            }
        }

#pragma unroll
        for (int kk = 0; kk < BK; kk++) {
            float ra[8], rb[8];
#pragma unroll
            for (int i = 0; i < 8; i++) ra[i] = As[cur][kk][ty * 8 + i];
#pragma unroll
            for (int j = 0; j < 8; j++) rb[j] = Bs[cur][kk][tx * 8 + j];
#pragma unroll
            for (int i = 0; i < 8; i++)
#pragma unroll
                for (int j = 0; j < 8; j++)
                    acc[i][j] = __fmaf_rn(ra[i], rb[j], acc[i][j]);
        }

        if (it + 1 < NIT) {
            As[nxt][lCol + 0][lRow] = av.x; As[nxt][lCol + 1][lRow] = av.y;
            As[nxt][lCol + 2][lRow] = av.z; As[nxt][lCol + 3][lRow] = av.w;
            Bs[nxt][lCol + 0][lRow] = wv.x; Bs[nxt][lCol + 1][lRow] = wv.y;
            Bs[nxt][lCol + 2][lRow] = wv.z; Bs[nxt][lCol + 3][lRow] = wv.w;
        }
        __syncthreads();

        // Eigen panel boundary: fold partial into C (gmem), left-to-right.
        int knext = (it + 1) * BK;
        if ((knext % KC) == 0 || knext >= K) {
            if (panel_done == 0) {
#pragma unroll
                for (int i = 0; i < 8; i++) {
                    float* crow = cbase + (size_t)i * H;
#pragma unroll
                    for (int j = 0; j < 8; j += 4)
                        *(float4*)(crow + j) = make_float4(acc[i][j], acc[i][j+1],
                                                           acc[i][j+2], acc[i][j+3]);
                }
            } else {
#pragma unroll
                for (int i = 0; i < 8; i++) {
                    float* crow = cbase + (size_t)i * H;
#pragma unroll
                    for (int j = 0; j < 8; j += 4) {
                        float4 c = *(float4*)(crow + j);
                        c.x = __fadd_rn(c.x, acc[i][j    ]);
                        c.y = __fadd_rn(c.y, acc[i][j + 1]);
                        c.z = __fadd_rn(c.z, acc[i][j + 2]);
                        c.w = __fadd_rn(c.w, acc[i][j + 3]);
                        *(float4*)(crow + j) = c;
                    }
                }
            }
            panel_done++;
#pragma unroll
            for (int i = 0; i < 8; i++)
#pragma unroll
                for (int j = 0; j < 8; j++) acc[i][j] = 0.f;
        }
    }

    // Signal: this tile (128 M-rows, all within one timestep) is complete.
    __threadfence();
    __syncthreads();
    if (tid == 0) atomicAdd(&g_cnt[block_m >> 11], 1);   // 2048 rows per t
}

// ---------------------------------------------------------------------------
// Persistent LIF scan (R8 structure, verified): 8 rows/block, 512 threads,
// two rows per thread, per-row-group named barriers, double-buffered state.
// Adds a per-timestep acquire-poll on g_cnt[t] so it can run concurrently
// with (the tail of) the GEMM.
// ---------------------------------------------------------------------------
#define ROWS_PB 8
#define SCAN_THREADS 512
#define V1T_STRIDE 129
#define V1T_ELEMS (128 * V1T_STRIDE)
#define W2_STRIDE 129
#define SCAN_SMEM_FLOATS (V1T_ELEMS + OUT_N * W2_STRIDE + 2*ROWS_PB*OUT_N + 2*ROWS_PB*4)
#define SCAN_SMEM_BYTES (SCAN_SMEM_FLOATS * 4)

__global__ __launch_bounds__(SCAN_THREADS, 2)
void scan_kernel(const float* __restrict__ b1, const float* __restrict__ V1,
                 const float* __restrict__ bV1, const float* __restrict__ W2,
                 const float* __restrict__ b2, const float* __restrict__ V2,
                 const float* __restrict__ bV2, float* __restrict__ out) {
    extern __shared__ float smem[];
    float* V1t   = smem;                                  // [j*129 + h] = V1[h][j]
    float* W2s   = smem + V1T_ELEMS;                      // [o*129 + j]
    float* sspk2 = W2s + OUT_N * W2_STRIDE;               // [buf][row][10]
    unsigned* s_mask = (unsigned*)(sspk2 + 2 * ROWS_PB * OUT_N); // [buf][row][4]

    int tid  = threadIdx.x;
    int h    = tid & 127;
    int q    = tid >> 7;             // row group 0..3; thread owns rows q and q+4
    int rA   = q;
    int rB   = q + 4;
    int bA   = blockIdx.x * ROWS_PB + rA;
    int bB   = blockIdx.x * ROWS_PB + rB;
    int wid  = tid >> 5;             // warp 0..15; group = wid>>2, word = wid&3
    int word = wid & 3;

    for (int idx = tid; idx < 128 * 128; idx += SCAN_THREADS) {
        int rr = idx >> 7, cc = idx & 127;
        V1t[cc * V1T_STRIDE + rr] = V1[idx];
    }
    for (int idx = tid; idx < OUT_N * 128; idx += SCAN_THREADS) {
        int o = idx >> 7, j = idx & 127;
        W2s[o * W2_STRIDE + j] = W2[idx];
    }
    if (tid < 2 * ROWS_PB * OUT_N) sspk2[tid] = 0.f;
    if (tid < 2 * ROWS_PB * 4) s_mask[tid] = 0u;

    float V2row[OUT_N];
    float b2h = 0.f, bV2h = 0.f, mem2A = 0.f, mem2B = 0.f;
    if (h < OUT_N) {
#pragma unroll
        for (int p = 0; p < OUT_N; p++) V2row[p] = V2[h * OUT_N + p];
        b2h = b2[h]; bV2h = bV2[h];
    }

    float b1h  = b1[h];
    float bV1h = bV1[h];
    float mem1A = 0.f, mem1B = 0.f;
    const float* curA = g_cur1 + (size_t)bA * H + h;
    const float* curB = g_cur1 + (size_t)bB * H + h;
    float* outA = out + (size_t)bA * OUT_N + h;
    float* outB = out + (size_t)bB * OUT_N + h;
    const float* colh = V1t + h;
    __syncthreads();                 // V1t/W2s/init visible to all

    for (int t = 0; t < T_STEPS; t++) {
        int pw = t & 1;
        int pr = pw ^ 1;

        // Wait until all 16 GEMM tiles for timestep t are complete.
        while (ld_acquire_gpu(&g_cnt[t]) < 16) __nanosleep(200);

        // ---- layer 1 rec terms for both rows (independent chains) ----
        float recA = 0.f, recB = 0.f;
#pragma unroll
        for (int w = 0; w < 4; w++) {
            unsigned mA = s_mask[(pr * ROWS_PB + rA) * 4 + w];
            unsigned mB = s_mask[(pr * ROWS_PB + rB) * 4 + w];
            const float* base = colh + (w * 32) * V1T_STRIDE;
            while (mA) {
                int j = __ffs(mA) - 1; mA &= mA - 1;
                recA = __fadd_rn(recA, base[j * V1T_STRIDE]);
            }
            while (mB) {
                int j = __ffs(mB) - 1; mB &= mB - 1;
                recB = __fadd_rn(recB, base[j * V1T_STRIDE]);
            }
        }

        float gvA = curA[(size_t)t * BATCH * H];
        float gvB = curB[(size_t)t * BATCH * H];

        float aA = __fmul_rn(0.9f, mem1A);
        aA = __fadd_rn(aA, __fadd_rn(gvA, b1h));
        aA = __fadd_rn(aA, recA);
        aA = __fadd_rn(aA, bV1h);
        float resetA = (mem1A > 1.0f) ? 1.0f : 0.0f;
        mem1A = __fsub_rn(aA, resetA);
        float spkA = (mem1A > 1.0f) ? 1.0f : 0.0f;

        float aB = __fmul_rn(0.9f, mem1B);
        aB = __fadd_rn(aB, __fadd_rn(gvB, b1h));
        aB = __fadd_rn(aB, recB);
        aB = __fadd_rn(aB, bV1h);
        float resetB = (mem1B > 1.0f) ? 1.0f : 0.0f;
        mem1B = __fsub_rn(aB, resetB);
        float spkB = (mem1B > 1.0f) ? 1.0f : 0.0f;

        unsigned balA = __ballot_sync(0xffffffffu, spkA != 0.0f);
        unsigned balB = __ballot_sync(0xffffffffu, spkB != 0.0f);
        if ((tid & 31) == 0) {
            s_mask[(pw * ROWS_PB + rA) * 4 + word] = balA;
            s_mask[(pw * ROWS_PB + rB) * 4 + word] = balB;
        }
        // per-row-group barrier: syncs the 4 warps (128 threads) of group q
        asm volatile("bar.sync %0, 128;" :: "r"(1 + q) : "memory");

        // ---- layer 2 for both rows (lanes h<10 of first warp of group) ----
        if (h < OUT_N) {
            const float* w2 = W2s + h * W2_STRIDE;
            float c2A = 0.f, c2B = 0.f;
#pragma unroll
            for (int w = 0; w < 4; w++) {
                unsigned nA = s_mask[(pw * ROWS_PB + rA) * 4 + w];
                unsigned nB = s_mask[(pw * ROWS_PB + rB) * 4 + w];
                const float* base = w2 + w * 32;
                while (nA) {
                    int j = __ffs(nA) - 1; nA &= nA - 1;
                    c2A = __fadd_rn(c2A, base[j]);
                }
                while (nB) {
                    int j = __ffs(nB) - 1; nB &= nB - 1;
                    c2B = __fadd_rn(c2B, base[j]);
                }
            }
            float rec2A = 0.f, rec2B = 0.f;
            const float* spA = sspk2 + (pr * ROWS_PB + rA) * OUT_N;
            const float* spB = sspk2 + (pr * ROWS_PB + rB) * OUT_N;
#pragma unroll
            for (int p = 0; p < OUT_N; p++) {
                if (spA[p] != 0.0f) rec2A = __fadd_rn(rec2A, V2row[p]);
                if (spB[p] != 0.0f) rec2B = __fadd_rn(rec2B, V2row[p]);
            }
            float uA = __fmul_rn(0.9f, mem2A);
            uA = __fadd_rn(uA, __fadd_rn(c2A, b2h));
            uA = __fadd_rn(uA, rec2A);
            uA = __fadd_rn(uA, bV2h);
            float reset2A = (mem2A > 1.0f) ? 1.0f : 0.0f;
            mem2A = __fsub_rn(uA, reset2A);
            float s2A = (mem2A > 1.0f) ? 1.0f : 0.0f;

            float uB = __fmul_rn(0.9f, mem2B);
            uB = __fadd_rn(uB, __fadd_rn(c2B, b2h));
            uB = __fadd_rn(uB, rec2B);
            uB = __fadd_rn(uB, bV2h);
            float reset2B = (mem2B > 1.0f) ? 1.0f : 0.0f;
            mem2B = __fsub_rn(uB, reset2B);
            float s2B = (mem2B > 1.0f) ? 1.0f : 0.0f;

            outA[(size_t)t * BATCH * OUT_N] = s2A;
            outB[(size_t)t * BATCH * OUT_N] = s2B;
            sspk2[(pw * ROWS_PB + rA) * OUT_N + h] = s2A;
            sspk2[(pw * ROWS_PB + rB) * OUT_N + h] = s2B;
        }
        // next step's group barrier orders these writes vs reads at t+1
    }
}

extern "C" void kernel_launch(void* const* d_in, const int* in_sizes, int n_in,
                              void* d_out, int out_size) {
    const float* x   = (const float*)d_in[0];
    const float* W1  = (const float*)d_in[1];
    const float* b1  = (const float*)d_in[2];
    const float* V1  = (const float*)d_in[3];
    const float* bV1 = (const float*)d_in[4];
    const float* W2  = (const float*)d_in[5];
    const float* b2  = (const float*)d_in[6];
    const float* V2  = (const float*)d_in[7];
    const float* bV2 = (const float*)d_in[8];
    float* out = (float*)d_out;

    cudaFuncSetAttribute(scan_kernel, cudaFuncAttributeMaxDynamicSharedMemorySize,
                         SCAN_SMEM_BYTES);

    // Zero the per-timestep completion counters (captured async memset).
    void* cnt_addr = nullptr;
    cudaGetSymbolAddress(&cnt_addr, g_cnt);
    cudaMemsetAsync(cnt_addr, 0, T_STEPS * sizeof(int), 0);

    // Fork a side stream for the scan so it can overlap the GEMM tail.
    cudaStream_t s2;
    cudaStreamCreateWithFlags(&s2, cudaStreamNonBlocking);
    cudaEvent_t eF, eJ;
    cudaEventCreateWithFlags(&eF, cudaEventDisableTiming);
    cudaEventCreateWithFlags(&eJ, cudaEventDisableTiming);

    cudaEventRecord(eF, 0);           // after memset on the capture stream
    cudaStreamWaitEvent(s2, eF, 0);

    const int M = T_STEPS * BATCH;    // 102400
    // GEMM launched FIRST: its 800 blocks are dispatched ahead of the scan's
    // (FIFO), so the scan can never starve the GEMM -> no deadlock.
    gemm_xw1<<<M / 128, 256, 0, 0>>>(x, W1, M, D_IN);
    scan_kernel<<<BATCH / ROWS_PB, SCAN_THREADS, SCAN_SMEM_BYTES, s2>>>(
        b1, V1, bV1, W2, b2, V2, bV2, out);

    cudaEventRecord(eJ, s2);          // join scan back into the capture stream
    cudaStreamWaitEvent(0, eJ, 0);

    cudaEventDestroy(eF);
    cudaEventDestroy(eJ);
    cudaStreamDestroy(s2);
}